// round 9
// baseline (speedup 1.0000x reference)
#include <cuda_runtime.h>
#include <cuda_bf16.h>
#include <cstdint>

#define D 128
#define MAX_NODES 50000
#define MAX_EDGES 800000

// Scratch (no device allocs allowed -> static __device__).
__device__ float g_aggr[(size_t)MAX_NODES * D];
__device__ int g_deg[MAX_NODES];
__device__ int g_start[MAX_NODES];
__device__ int g_cursor[MAX_NODES];
__device__ int g_ssrc[MAX_EDGES];

// ---------------------------------------------------------------------------
// CSR build: zero degrees -> histogram -> exclusive scan -> reorder.
// ---------------------------------------------------------------------------
__global__ void zero_deg_kernel(int* __restrict__ deg, int n) {
    int i = blockIdx.x * blockDim.x + threadIdx.x;
    if (i < n) deg[i] = 0;
}

__global__ void hist_kernel(const int* __restrict__ edst, int* __restrict__ deg,
                            int E) {
    int i = blockIdx.x * blockDim.x + threadIdx.x;
    if (i < E) atomicAdd(&deg[__ldg(&edst[i])], 1);
}

// Single-CTA exclusive scan over n<=~64k degrees (1024 threads, chunked).
__global__ __launch_bounds__(1024)
void scan_kernel(const int* __restrict__ deg, int* __restrict__ start,
                 int* __restrict__ cursor, int n) {
    __shared__ int warp_sums[32];
    int tid = threadIdx.x;
    int lane = tid & 31, w = tid >> 5;
    int ch = (n + 1023) >> 10;
    int base = tid * ch;

    int sum = 0;
    for (int i = 0; i < ch; i++) {
        int idx = base + i;
        if (idx < n) sum += __ldg(&deg[idx]);
    }
    // inclusive warp scan of per-thread sums
    int v = sum;
#pragma unroll
    for (int o = 1; o < 32; o <<= 1) {
        int t = __shfl_up_sync(0xffffffffu, v, o);
        if (lane >= o) v += t;
    }
    if (lane == 31) warp_sums[w] = v;
    __syncthreads();
    if (w == 0) {
        int s = warp_sums[lane];
#pragma unroll
        for (int o = 1; o < 32; o <<= 1) {
            int t = __shfl_up_sync(0xffffffffu, s, o);
            if (lane >= o) s += t;
        }
        warp_sums[lane] = s;
    }
    __syncthreads();
    int run = (v - sum) + (w > 0 ? warp_sums[w - 1] : 0);
    for (int i = 0; i < ch; i++) {
        int idx = base + i;
        if (idx < n) {
            start[idx] = run;
            cursor[idx] = run;
            run += __ldg(&deg[idx]);
        }
    }
}

__global__ void reorder_kernel(const int* __restrict__ esrc,
                               const int* __restrict__ edst,
                               int* __restrict__ cursor,
                               int* __restrict__ ssrc, int E) {
    int i = blockIdx.x * blockDim.x + threadIdx.x;
    if (i < E) {
        int pos = atomicAdd(&cursor[__ldg(&edst[i])], 1);
        ssrc[pos] = __ldg(&esrc[i]);
    }
}

// ---------------------------------------------------------------------------
// Gather: one warp per destination node. Lanes cooperatively fetch up to 32
// edge src indices, shfl-broadcast them, and each lane accumulates its 16B
// column slice of the neighbour rows in registers. One float4 store per row.
// No atomics; x (25.6 MB) stays L2-resident.
// ---------------------------------------------------------------------------
__global__ void gather_kernel(const float* __restrict__ x,
                              const int* __restrict__ ssrc,
                              const int* __restrict__ start,
                              const int* __restrict__ deg,
                              float* __restrict__ aggr, int N) {
    int gid = blockIdx.x * blockDim.x + threadIdx.x;
    int node = gid >> 5;
    int lane = gid & 31;
    if (node >= N) return;
    int s0 = __ldg(&start[node]);
    int dg = __ldg(&deg[node]);

    float4 acc = make_float4(0.f, 0.f, 0.f, 0.f);
    for (int eb = 0; eb < dg; eb += 32) {
        int cnt = min(32, dg - eb);
        int sidx = (lane < cnt) ? __ldg(&ssrc[s0 + eb + lane]) : 0;
#pragma unroll 4
        for (int j = 0; j < cnt; j++) {
            int s = __shfl_sync(0xffffffffu, sidx, j);
            float4 v = __ldg(reinterpret_cast<const float4*>(x + (size_t)s * D) + lane);
            acc.x += v.x; acc.y += v.y; acc.z += v.z; acc.w += v.w;
        }
    }
    reinterpret_cast<float4*>(aggr + (size_t)node * D)[lane] = acc;
}

// ---------------------------------------------------------------------------
// tf32 mma.sync GEMM (unchanged from R6 win).
//   out[n][o] = sum_k [x|aggr][n][k] * [W1|W2][o][k] + (b1+b2)[o]
// ---------------------------------------------------------------------------
#define BM 128
#define GT 256
#define LDA 33

__device__ __forceinline__ float to_tf32(float f) {
    uint32_t u;
    asm("cvt.rna.tf32.f32 %0, %1;" : "=r"(u) : "f"(f));
    return __uint_as_float(u);
}

__device__ __forceinline__ void mma1688(float* c, const uint32_t* a,
                                        const uint32_t* b) {
    asm volatile(
        "mma.sync.aligned.m16n8k8.row.col.f32.tf32.tf32.f32 "
        "{%0,%1,%2,%3}, {%4,%5,%6,%7}, {%8,%9}, {%0,%1,%2,%3};"
        : "+f"(c[0]), "+f"(c[1]), "+f"(c[2]), "+f"(c[3])
        : "r"(a[0]), "r"(a[1]), "r"(a[2]), "r"(a[3]), "r"(b[0]), "r"(b[1]));
}

__global__ __launch_bounds__(GT, 1)
void gemm_mma(const float* __restrict__ x, const float* __restrict__ aggr,
              const float* __restrict__ W1, const float* __restrict__ W2,
              const float* __restrict__ b1, const float* __restrict__ b2,
              float* __restrict__ out, int N) {
    __shared__ float As[BM][LDA];     // [row][k]
    __shared__ float Bs[128][LDA];    // [out-col][k]
    __shared__ float sbias[128];

    int tid = threadIdx.x;
    int warp = tid >> 5, lane = tid & 31;
    int wm = warp & 3;
    int wn = warp >> 2;
    int g = lane >> 2;
    int t = lane & 3;
    int row0 = blockIdx.x * BM;

    if (tid < 128) sbias[tid] = __ldg(&b1[tid]) + __ldg(&b2[tid]);

    float acc[2][8][4];
#pragma unroll
    for (int mi = 0; mi < 2; mi++)
#pragma unroll
        for (int ni = 0; ni < 8; ni++)
#pragma unroll
            for (int c = 0; c < 4; c++) acc[mi][ni][c] = 0.f;

#pragma unroll 1
    for (int kb = 0; kb < 8; kb++) {
        const float* asrc = (kb < 4) ? x : aggr;
        const float* bsrc = (kb < 4) ? W1 : W2;
        int k0 = (kb & 3) * 32;

        __syncthreads();
#pragma unroll
        for (int i = 0; i < 4; i++) {
            int f = tid + i * GT;
            int r = f >> 3, c = (f & 7) * 4;
            int grow = row0 + r;
            float4 v = make_float4(0.f, 0.f, 0.f, 0.f);
            if (grow < N)
                v = *reinterpret_cast<const float4*>(asrc + (size_t)grow * D + k0 + c);
            As[r][c + 0] = to_tf32(v.x);
            As[r][c + 1] = to_tf32(v.y);
            As[r][c + 2] = to_tf32(v.z);
            As[r][c + 3] = to_tf32(v.w);
            float4 w2 = *reinterpret_cast<const float4*>(bsrc + (size_t)r * D + k0 + c);
            Bs[r][c + 0] = to_tf32(w2.x);
            Bs[r][c + 1] = to_tf32(w2.y);
            Bs[r][c + 2] = to_tf32(w2.z);
            Bs[r][c + 3] = to_tf32(w2.w);
        }
        __syncthreads();

#pragma unroll
        for (int ks = 0; ks < 4; ks++) {
            int k8 = ks * 8;
            uint32_t a[2][4];
#pragma unroll
            for (int mi = 0; mi < 2; mi++) {
                int rb = wm * 32 + mi * 16;
                a[mi][0] = __float_as_uint(As[rb + g][k8 + t]);
                a[mi][1] = __float_as_uint(As[rb + g + 8][k8 + t]);
                a[mi][2] = __float_as_uint(As[rb + g][k8 + t + 4]);
                a[mi][3] = __float_as_uint(As[rb + g + 8][k8 + t + 4]);
            }
            uint32_t b[8][2];
#pragma unroll
            for (int ni = 0; ni < 8; ni++) {
                int cb = wn * 64 + ni * 8;
                b[ni][0] = __float_as_uint(Bs[cb + g][k8 + t]);
                b[ni][1] = __float_as_uint(Bs[cb + g][k8 + t + 4]);
            }
#pragma unroll
            for (int mi = 0; mi < 2; mi++)
#pragma unroll
                for (int ni = 0; ni < 8; ni++)
                    mma1688(acc[mi][ni], a[mi], b[ni]);
        }
    }

#pragma unroll
    for (int mi = 0; mi < 2; mi++) {
        int r_lo = row0 + wm * 32 + mi * 16 + g;
#pragma unroll
        for (int ni = 0; ni < 8; ni++) {
            int col = wn * 64 + ni * 8 + t * 2;
            float bx = sbias[col], by = sbias[col + 1];
            if (r_lo < N) {
                float2 v = make_float2(acc[mi][ni][0] + bx, acc[mi][ni][1] + by);
                *reinterpret_cast<float2*>(out + (size_t)r_lo * D + col) = v;
            }
            if (r_lo + 8 < N) {
                float2 v = make_float2(acc[mi][ni][2] + bx, acc[mi][ni][3] + by);
                *reinterpret_cast<float2*>(out + (size_t)(r_lo + 8) * D + col) = v;
            }
        }
    }
}

// ---------------------------------------------------------------------------
// launch
// ---------------------------------------------------------------------------
extern "C" void kernel_launch(void* const* d_in, const int* in_sizes, int n_in,
                              void* d_out, int out_size) {
    const float* x    = (const float*)d_in[0];   // [N, 128]
    const float* W1   = (const float*)d_in[1];   // [128, 128]
    const float* b1   = (const float*)d_in[2];   // [128]
    const float* W2   = (const float*)d_in[3];   // [128, 128]
    const float* b2   = (const float*)d_in[4];   // [128]
    const int*   esrc = (const int*)d_in[5];     // [E]
    const int*   edst = (const int*)d_in[6];     // [E]
    float* out = (float*)d_out;

    int N = in_sizes[0] / D;
    int E = in_sizes[5];
    if (N > MAX_NODES) N = MAX_NODES;
    if (E > MAX_EDGES) E = MAX_EDGES;

    float* aggr = nullptr;
    int *deg = nullptr, *start = nullptr, *cursor = nullptr, *ssrc = nullptr;
    cudaGetSymbolAddress((void**)&aggr, g_aggr);
    cudaGetSymbolAddress((void**)&deg, g_deg);
    cudaGetSymbolAddress((void**)&start, g_start);
    cudaGetSymbolAddress((void**)&cursor, g_cursor);
    cudaGetSymbolAddress((void**)&ssrc, g_ssrc);

    // 1) CSR build
    zero_deg_kernel<<<(N + 255) / 256, 256>>>(deg, N);
    hist_kernel<<<(E + 255) / 256, 256>>>(edst, deg, E);
    scan_kernel<<<1, 1024>>>(deg, start, cursor, N);
    reorder_kernel<<<(E + 255) / 256, 256>>>(esrc, edst, cursor, ssrc, E);

    // 2) gather (warp per dst node, no atomics)
    {
        long long total = (long long)N * 32;
        int blocks = (int)((total + 255) / 256);
        gather_kernel<<<blocks, 256>>>(x, ssrc, start, deg, aggr, N);
    }

    // 3) tf32 mma.sync GEMM
    {
        int blocks = (N + BM - 1) / BM;
        gemm_mma<<<blocks, GT>>>(x, aggr, W1, W2, b1, b2, out, N);
    }
}

// round 10
// speedup vs baseline: 1.3280x; 1.3280x over previous
#include <cuda_runtime.h>
#include <cuda_bf16.h>
#include <cstdint>

#define D 128
#define MAX_NODES 50000

// y2 = x @ W2^T scratch (no device allocs allowed -> static __device__).
__device__ float g_y2[(size_t)MAX_NODES * D];

// ---------------------------------------------------------------------------
// Kernel 1: fused tf32 mma.sync GEMM, K=128, 256 output columns:
//   cols   0..127: out[n][o] = sum_k x[n][k]*W1[o][k] + (b1+b2)[o]
//   cols 128..255: y2[n][o]  = sum_k x[n][k]*W2[o][k]
// CTA: BM=128 rows, 16 warps; warp tile 32x64 (2 m-frags x 8 n-frags m16n8k8).
// A tile read ONCE per k-chunk and shared by both weight matrices.
// ---------------------------------------------------------------------------
#define BM 128
#define GT 512
#define LDA 33

__device__ __forceinline__ float to_tf32(float f) {
    uint32_t u;
    asm("cvt.rna.tf32.f32 %0, %1;" : "=r"(u) : "f"(f));
    return __uint_as_float(u);
}

__device__ __forceinline__ void mma1688(float* c, const uint32_t* a,
                                        const uint32_t* b) {
    asm volatile(
        "mma.sync.aligned.m16n8k8.row.col.f32.tf32.tf32.f32 "
        "{%0,%1,%2,%3}, {%4,%5,%6,%7}, {%8,%9}, {%0,%1,%2,%3};"
        : "+f"(c[0]), "+f"(c[1]), "+f"(c[2]), "+f"(c[3])
        : "r"(a[0]), "r"(a[1]), "r"(a[2]), "r"(a[3]), "r"(b[0]), "r"(b[1]));
}

__global__ __launch_bounds__(GT, 1)
void gemm_fused(const float* __restrict__ x,
                const float* __restrict__ W1, const float* __restrict__ W2,
                const float* __restrict__ b1, const float* __restrict__ b2,
                float* __restrict__ out, float* __restrict__ y2, int N) {
    extern __shared__ float sm[];
    float (*As)[LDA] = reinterpret_cast<float(*)[LDA]>(sm);            // [128][33]
    float (*Bs)[LDA] = reinterpret_cast<float(*)[LDA]>(sm + 128 * LDA); // [256][33]
    float* sbias = sm + (128 + 256) * LDA;                              // [128]

    int tid = threadIdx.x;
    int warp = tid >> 5, lane = tid & 31;
    int wm = warp & 3;          // rows wm*32 .. +31
    int wn = warp >> 2;         // combined cols wn*64 .. +63  (wn: 0..3)
    int g = lane >> 2;
    int t = lane & 3;
    int row0 = blockIdx.x * BM;

    if (tid < 128) sbias[tid] = __ldg(&b1[tid]) + __ldg(&b2[tid]);

    float acc[2][8][4];
#pragma unroll
    for (int mi = 0; mi < 2; mi++)
#pragma unroll
        for (int ni = 0; ni < 8; ni++)
#pragma unroll
            for (int c = 0; c < 4; c++) acc[mi][ni][c] = 0.f;

#pragma unroll 1
    for (int kb = 0; kb < 4; kb++) {
        int k0 = kb * 32;

        __syncthreads();
        // As: 128x32 = 1024 float4 -> 2 per thread.
#pragma unroll
        for (int i = 0; i < 2; i++) {
            int f = tid + i * GT;
            int r = f >> 3, c = (f & 7) * 4;
            int grow = row0 + r;
            float4 v = make_float4(0.f, 0.f, 0.f, 0.f);
            if (grow < N)
                v = *reinterpret_cast<const float4*>(x + (size_t)grow * D + k0 + c);
            As[r][c + 0] = to_tf32(v.x);
            As[r][c + 1] = to_tf32(v.y);
            As[r][c + 2] = to_tf32(v.z);
            As[r][c + 3] = to_tf32(v.w);
        }
        // Bs: 256x32 = 2048 float4 -> 4 per thread (rows 0..127 W1, 128..255 W2).
#pragma unroll
        for (int i = 0; i < 4; i++) {
            int f = tid + i * GT;
            int r = f >> 3, c = (f & 7) * 4;
            const float* wsrc = (r < 128) ? (W1 + (size_t)r * D)
                                          : (W2 + (size_t)(r - 128) * D);
            float4 w = *reinterpret_cast<const float4*>(wsrc + k0 + c);
            Bs[r][c + 0] = to_tf32(w.x);
            Bs[r][c + 1] = to_tf32(w.y);
            Bs[r][c + 2] = to_tf32(w.z);
            Bs[r][c + 3] = to_tf32(w.w);
        }
        __syncthreads();

#pragma unroll
        for (int ks = 0; ks < 4; ks++) {
            int k8 = ks * 8;
            uint32_t a[2][4];
#pragma unroll
            for (int mi = 0; mi < 2; mi++) {
                int rb = wm * 32 + mi * 16;
                a[mi][0] = __float_as_uint(As[rb + g][k8 + t]);
                a[mi][1] = __float_as_uint(As[rb + g + 8][k8 + t]);
                a[mi][2] = __float_as_uint(As[rb + g][k8 + t + 4]);
                a[mi][3] = __float_as_uint(As[rb + g + 8][k8 + t + 4]);
            }
            uint32_t b[8][2];
#pragma unroll
            for (int ni = 0; ni < 8; ni++) {
                int cb = wn * 64 + ni * 8;
                b[ni][0] = __float_as_uint(Bs[cb + g][k8 + t]);
                b[ni][1] = __float_as_uint(Bs[cb + g][k8 + t + 4]);
            }
#pragma unroll
            for (int mi = 0; mi < 2; mi++)
#pragma unroll
                for (int ni = 0; ni < 8; ni++)
                    mma1688(acc[mi][ni], a[mi], b[ni]);
        }
    }

    // Epilogue. wn<2 -> out (bias added); wn>=2 -> y2 (cols-128, no bias).
    bool is_out = (wn < 2);
    float* dst = is_out ? out : y2;
    int colbase = is_out ? (wn * 64) : (wn * 64 - 128);
#pragma unroll
    for (int mi = 0; mi < 2; mi++) {
        int r_lo = row0 + wm * 32 + mi * 16 + g;
#pragma unroll
        for (int ni = 0; ni < 8; ni++) {
            int col = colbase + ni * 8 + t * 2;
            float bx = is_out ? sbias[col] : 0.f;
            float by = is_out ? sbias[col + 1] : 0.f;
            if (r_lo < N) {
                float2 v = make_float2(acc[mi][ni][0] + bx, acc[mi][ni][1] + by);
                *reinterpret_cast<float2*>(dst + (size_t)r_lo * D + col) = v;
            }
            if (r_lo + 8 < N) {
                float2 v = make_float2(acc[mi][ni][2] + bx, acc[mi][ni][3] + by);
                *reinterpret_cast<float2*>(dst + (size_t)(r_lo + 8) * D + col) = v;
            }
        }
    }
}

// ---------------------------------------------------------------------------
// Kernel 2: edge scatter, straight into out. One warp per edge:
//   lane l: v = y2[src][4l..4l+3];  red.global.add.v4.f32 out[dst][4l..] += v
// y2 (25.6 MB) is L2-resident; v4 reds quarter the atomic-op count.
// ---------------------------------------------------------------------------
__global__ void scatter_kernel(const float* __restrict__ y2,
                               const int* __restrict__ esrc,
                               const int* __restrict__ edst,
                               float* __restrict__ out, int E) {
    int gid = blockIdx.x * blockDim.x + threadIdx.x;
    int e = gid >> 5;
    int lane = gid & 31;
    if (e >= E) return;
    int s = __ldg(&esrc[e]);
    int d = __ldg(&edst[e]);
    const float4* yr = reinterpret_cast<const float4*>(y2 + (size_t)s * D);
    float4 v = __ldg(&yr[lane]);
    float* ap = out + (size_t)d * D + lane * 4;
    asm volatile("red.global.add.v4.f32 [%0], {%1, %2, %3, %4};"
                 :: "l"(ap), "f"(v.x), "f"(v.y), "f"(v.z), "f"(v.w)
                 : "memory");
}

// ---------------------------------------------------------------------------
// launch
// ---------------------------------------------------------------------------
extern "C" void kernel_launch(void* const* d_in, const int* in_sizes, int n_in,
                              void* d_out, int out_size) {
    const float* x    = (const float*)d_in[0];   // [N, 128]
    const float* W1   = (const float*)d_in[1];   // [128, 128]
    const float* b1   = (const float*)d_in[2];   // [128]
    const float* W2   = (const float*)d_in[3];   // [128, 128]
    const float* b2   = (const float*)d_in[4];   // [128]
    const int*   esrc = (const int*)d_in[5];     // [E]
    const int*   edst = (const int*)d_in[6];     // [E]
    float* out = (float*)d_out;

    int N = in_sizes[0] / D;
    int E = in_sizes[5];
    if (N > MAX_NODES) N = MAX_NODES;

    float* y2 = nullptr;
    cudaGetSymbolAddress((void**)&y2, g_y2);

    // 1) fused GEMM: out = x@W1^T + b, y2 = x@W2^T
    {
        size_t smem = ((128 + 256) * LDA + 128) * sizeof(float);  // ~51.2 KB
        cudaFuncSetAttribute(gemm_fused,
                             cudaFuncAttributeMaxDynamicSharedMemorySize,
                             (int)smem);
        int blocks = (N + BM - 1) / BM;
        gemm_fused<<<blocks, GT, smem>>>(x, W1, W2, b1, b2, out, y2, N);
    }

    // 2) edge scatter: out[dst] += y2[src]
    {
        int threads = 256;
        long long total = (long long)E * 32;
        int blocks = (int)((total + threads - 1) / threads);
        scatter_kernel<<<blocks, threads>>>(y2, esrc, edst, out, E);
    }
}

// round 13
// speedup vs baseline: 1.7354x; 1.3067x over previous
#include <cuda_runtime.h>
#include <cuda_bf16.h>
#include <cstdint>

#define D 128
#define MAX_NODES 50000

// y2 = x @ W2^T scratch (no device allocs allowed -> static __device__).
__device__ float g_y2[(size_t)MAX_NODES * D];

// ---------------------------------------------------------------------------
// Kernel 1: fused tf32 mma.sync GEMM, K=128, 256 output columns:
//   cols   0..127: out[n][o] = sum_k x[n][k]*W1[o][k] + (b1+b2)[o]
//   cols 128..255: y2[n][o]  = sum_k x[n][k]*W2[o][k]
// CTA: BM=128 rows, 16 warps; warp tile 32x64 (2 m-frags x 8 n-frags m16n8k8).
// cp.async double-buffered k-chunks (32 wide); raw fp32 in smem, cvt.rna.tf32
// at fragment-consume time. LDA=36 -> frag loads hit 32 distinct banks.
// ---------------------------------------------------------------------------
#define BM 128
#define GT 512
#define LDA 36                               // floats per row (144B, 16B-aligned)
#define SBUF ((128 + 256) * LDA * 4)         // bytes per buffer (As+Bs)

__device__ __forceinline__ uint32_t s2u(const void* p) {
    uint32_t a;
    asm("{ .reg .u64 t; cvta.to.shared.u64 t, %1; cvt.u32.u64 %0, t; }"
        : "=r"(a) : "l"(p));
    return a;
}

__device__ __forceinline__ void cp16(uint32_t dst, const void* src, int srcsz) {
    asm volatile("cp.async.ca.shared.global [%0], [%1], 16, %2;"
                 :: "r"(dst), "l"(src), "r"(srcsz));
}

__device__ __forceinline__ uint32_t to_tf32_u(float f) {
    uint32_t u;
    asm("cvt.rna.tf32.f32 %0, %1;" : "=r"(u) : "f"(f));
    return u;
}

__device__ __forceinline__ void mma1688(float* c, const uint32_t* a,
                                        const uint32_t* b) {
    asm volatile(
        "mma.sync.aligned.m16n8k8.row.col.f32.tf32.tf32.f32 "
        "{%0,%1,%2,%3}, {%4,%5,%6,%7}, {%8,%9}, {%0,%1,%2,%3};"
        : "+f"(c[0]), "+f"(c[1]), "+f"(c[2]), "+f"(c[3])
        : "r"(a[0]), "r"(a[1]), "r"(a[2]), "r"(a[3]), "r"(b[0]), "r"(b[1]));
}

__global__ __launch_bounds__(GT, 1)
void gemm_fused(const float* __restrict__ x,
                const float* __restrict__ W1, const float* __restrict__ W2,
                const float* __restrict__ b1, const float* __restrict__ b2,
                float* __restrict__ out, float* __restrict__ y2, int N) {
    extern __shared__ __align__(16) float sm[];
    float* sbias = sm + 2 * SBUF / 4;        // [128] after the two buffers

    uint32_t smu = s2u(sm);
    int tid = threadIdx.x;
    int warp = tid >> 5, lane = tid & 31;
    int wm = warp & 3;          // rows wm*32 .. +31
    int wn = warp >> 2;         // combined cols wn*64 .. +63  (wn: 0..3)
    int g = lane >> 2;
    int t = lane & 3;
    int row0 = blockIdx.x * BM;

    if (tid < 128) sbias[tid] = __ldg(&b1[tid]) + __ldg(&b2[tid]);

    // ---- async tile fill: k-chunk kb into buffer (kb & 1) ----
    auto issue_tile = [&](int kb) {
        int k0 = kb * 32;
        uint32_t abase = smu + (kb & 1) * SBUF;
        uint32_t bbase = abase + 128 * LDA * 4;
        // As: 128 rows x 32 floats = 1024 cp16 -> 2 per thread
#pragma unroll
        for (int i = 0; i < 2; i++) {
            int f = tid + i * GT;
            int r = f >> 3, c4 = f & 7;          // c4*4 = float col
            int grow = row0 + r;
            int ok = (grow < N) ? 16 : 0;
            int srow = (grow < N) ? grow : (N - 1);
            cp16(abase + r * (LDA * 4) + c4 * 16,
                 x + (size_t)srow * D + k0 + c4 * 4, ok);
        }
        // Bs: 256 rows x 32 floats = 2048 cp16 -> 4 per thread
#pragma unroll
        for (int i = 0; i < 4; i++) {
            int f = tid + i * GT;
            int r = f >> 3, c4 = f & 7;
            const float* wsrc = (r < 128) ? (W1 + (size_t)r * D)
                                          : (W2 + (size_t)(r - 128) * D);
            cp16(bbase + r * (LDA * 4) + c4 * 16, wsrc + k0 + c4 * 4, 16);
        }
        asm volatile("cp.async.commit_group;");
    };

    float acc[2][8][4];
#pragma unroll
    for (int mi = 0; mi < 2; mi++)
#pragma unroll
        for (int ni = 0; ni < 8; ni++)
#pragma unroll
            for (int c = 0; c < 4; c++) acc[mi][ni][c] = 0.f;

    issue_tile(0);
    issue_tile(1);

#pragma unroll 1
    for (int kb = 0; kb < 4; kb++) {
        if (kb == 3) asm volatile("cp.async.wait_group 0;");
        else         asm volatile("cp.async.wait_group 1;");
        __syncthreads();

        const float* As = sm + (kb & 1) * (SBUF / 4);
        const float* Bs = As + 128 * LDA;

#pragma unroll
        for (int ks = 0; ks < 4; ks++) {
            int k8 = ks * 8;
            uint32_t a[2][4];
#pragma unroll
            for (int mi = 0; mi < 2; mi++) {
                int rb = wm * 32 + mi * 16;
                a[mi][0] = to_tf32_u(As[(rb + g) * LDA + k8 + t]);
                a[mi][1] = to_tf32_u(As[(rb + g + 8) * LDA + k8 + t]);
                a[mi][2] = to_tf32_u(As[(rb + g) * LDA + k8 + t + 4]);
                a[mi][3] = to_tf32_u(As[(rb + g + 8) * LDA + k8 + t + 4]);
            }
            uint32_t b[8][2];
#pragma unroll
            for (int ni = 0; ni < 8; ni++) {
                int cb = wn * 64 + ni * 8;
                b[ni][0] = to_tf32_u(Bs[(cb + g) * LDA + k8 + t]);
                b[ni][1] = to_tf32_u(Bs[(cb + g) * LDA + k8 + t + 4]);
            }
#pragma unroll
            for (int mi = 0; mi < 2; mi++)
#pragma unroll
                for (int ni = 0; ni < 8; ni++)
                    mma1688(acc[mi][ni], a[mi], b[ni]);
        }

        __syncthreads();                 // done reading buf (kb&1)
        if (kb + 2 < 4) issue_tile(kb + 2);
    }

    // Epilogue. wn<2 -> out (bias added); wn>=2 -> y2 (cols-128, no bias).
    bool is_out = (wn < 2);
    float* dst = is_out ? out : y2;
    int colbase = is_out ? (wn * 64) : (wn * 64 - 128);
#pragma unroll
    for (int mi = 0; mi < 2; mi++) {
        int r_lo = row0 + wm * 32 + mi * 16 + g;
#pragma unroll
        for (int ni = 0; ni < 8; ni++) {
            int col = colbase + ni * 8 + t * 2;
            float bx = is_out ? sbias[col] : 0.f;
            float by = is_out ? sbias[col + 1] : 0.f;
            if (r_lo < N) {
                float2 v = make_float2(acc[mi][ni][0] + bx, acc[mi][ni][1] + by);
                *reinterpret_cast<float2*>(dst + (size_t)r_lo * D + col) = v;
            }
            if (r_lo + 8 < N) {
                float2 v = make_float2(acc[mi][ni][2] + bx, acc[mi][ni][3] + by);
                *reinterpret_cast<float2*>(dst + (size_t)(r_lo + 8) * D + col) = v;
            }
        }
    }
}

// ---------------------------------------------------------------------------
// Kernel 2: edge scatter, 4 edges per warp for MLP:
//   batch 4 independent y2[src] float4 loads, then 4 RED.128s.
//   out[dst][4l..4l+3] += y2[src][4l..4l+3]
// ---------------------------------------------------------------------------
#define EPW 4

__global__ void scatter_kernel(const float* __restrict__ y2,
                               const int* __restrict__ esrc,
                               const int* __restrict__ edst,
                               float* __restrict__ out, int E) {
    int gid = blockIdx.x * blockDim.x + threadIdx.x;
    int lane = gid & 31;
    int e0 = (gid >> 5) * EPW;
    if (e0 >= E) return;

    float4 v[EPW];
    int dn[EPW];
#pragma unroll
    for (int j = 0; j < EPW; j++) {
        if (e0 + j < E) {
            int s = __ldg(&esrc[e0 + j]);
            dn[j] = __ldg(&edst[e0 + j]);
            v[j] = __ldg(reinterpret_cast<const float4*>(y2 + (size_t)s * D) + lane);
        }
    }
#pragma unroll
    for (int j = 0; j < EPW; j++) {
        if (e0 + j < E) {
            float* ap = out + (size_t)dn[j] * D + lane * 4;
            asm volatile("red.global.add.v4.f32 [%0], {%1, %2, %3, %4};"
                         :: "l"(ap), "f"(v[j].x), "f"(v[j].y), "f"(v[j].z),
                            "f"(v[j].w)
                         : "memory");
        }
    }
}

// ---------------------------------------------------------------------------
// launch
// ---------------------------------------------------------------------------
extern "C" void kernel_launch(void* const* d_in, const int* in_sizes, int n_in,
                              void* d_out, int out_size) {
    const float* x    = (const float*)d_in[0];   // [N, 128]
    const float* W1   = (const float*)d_in[1];   // [128, 128]
    const float* b1   = (const float*)d_in[2];   // [128]
    const float* W2   = (const float*)d_in[3];   // [128, 128]
    const float* b2   = (const float*)d_in[4];   // [128]
    const int*   esrc = (const int*)d_in[5];     // [E]
    const int*   edst = (const int*)d_in[6];     // [E]
    float* out = (float*)d_out;

    int N = in_sizes[0] / D;
    int E = in_sizes[5];
    if (N > MAX_NODES) N = MAX_NODES;

    float* y2 = nullptr;
    cudaGetSymbolAddress((void**)&y2, g_y2);

    // 1) fused GEMM: out = x@W1^T + b, y2 = x@W2^T  (cp.async double-buffered)
    {
        size_t smem = 2 * SBUF + 128 * sizeof(float);   // ~111 KB
        cudaFuncSetAttribute(gemm_fused,
                             cudaFuncAttributeMaxDynamicSharedMemorySize,
                             (int)smem);
        int blocks = (N + BM - 1) / BM;
        gemm_fused<<<blocks, GT, smem>>>(x, W1, W2, b1, b2, out, y2, N);
    }

    // 2) edge scatter: out[dst] += y2[src], 4 edges per warp
    {
        int threads = 256;
        long long warps = ((long long)E + EPW - 1) / EPW;
        int blocks = (int)((warps * 32 + threads - 1) / threads);
        scatter_kernel<<<blocks, threads>>>(y2, esrc, edst, out, E);
    }
}